// round 1
// baseline (speedup 1.0000x reference)
#include <cuda_runtime.h>
#include <cuda_bf16.h>

// CBC_34033320854004
// x           : [B, 1024] f32
// components  : [5, 1024] f32
// reasonings  : [5, 3, 2] f32
// out (probs) : [B, 3]    f32
//
// probs[b,c] = ( sum_k sims[b,k]*(pk-nk)[c,k] + sum_k nk[c,k] ) / sum_k (pk+nk)[c,k]
// sims[b,k]  = exp( -max(x2[b] + c2[k] - 2*dot(x_b, comp_k), 0) / 2 )

#define D_DIM 1024
#define K_DIM 5
#define C_DIM 3
#define THREADS 256
#define WARPS (THREADS / 32)
#define ROWS_PER_BLOCK 32              // 8 warps * 4 rows, processed 2 at a time
#define F4_PER_ROW (D_DIM / 4)         // 256 float4 per row
#define F4_PER_LANE (F4_PER_ROW / 32)  // 8 float4 per lane

__global__ __launch_bounds__(THREADS)
void cbc_kernel(const float* __restrict__ x,
                const float* __restrict__ comps,
                const float* __restrict__ reas,
                float* __restrict__ out,
                int B)
{
    __shared__ float s_comp[K_DIM * D_DIM];   // 20 KB
    __shared__ float s_c2[K_DIM];
    __shared__ float s_W[C_DIM][K_DIM];       // pk - nk
    __shared__ float s_bias[C_DIM];           // sum_k nk
    __shared__ float s_rden[C_DIM];           // 1 / sum_k (pk + nk)

    const int tid  = threadIdx.x;
    const int wid  = tid >> 5;
    const int lane = tid & 31;

    // ---- stage components into shared (vectorized) ----
    {
        const float4* src = reinterpret_cast<const float4*>(comps);
        float4* dst = reinterpret_cast<float4*>(s_comp);
        #pragma unroll
        for (int i = tid; i < K_DIM * F4_PER_ROW; i += THREADS)
            dst[i] = src[i];
    }

    // ---- reasonings -> W, bias, rden (single thread; tiny) ----
    if (tid == 0) {
        #pragma unroll
        for (int c = 0; c < C_DIM; ++c) {
            float bias = 0.f, den = 0.f;
            #pragma unroll
            for (int k = 0; k < K_DIM; ++k) {
                // reasonings layout [K, C, 2]
                float A  = reas[(k * C_DIM + c) * 2 + 0];
                float Bn = reas[(k * C_DIM + c) * 2 + 1];
                A  = fminf(fmaxf(A,  0.f), 1.f);
                Bn = fminf(fmaxf(Bn, 0.f), 1.f);
                float pk = A;
                float nk = (1.f - A) * Bn;
                s_W[c][k] = pk - nk;
                bias += nk;
                den  += pk + nk;
            }
            s_bias[c] = bias;
            s_rden[c] = 1.f / den;
        }
    }
    __syncthreads();

    // ---- c2[k]: one warp per component ----
    if (wid < K_DIM) {
        float acc = 0.f;
        const float4* cp = reinterpret_cast<const float4*>(s_comp + wid * D_DIM);
        #pragma unroll
        for (int j = 0; j < F4_PER_LANE; ++j) {
            float4 v = cp[lane + 32 * j];
            acc += v.x * v.x + v.y * v.y + v.z * v.z + v.w * v.w;
        }
        #pragma unroll
        for (int off = 16; off; off >>= 1)
            acc += __shfl_xor_sync(0xffffffffu, acc, off);
        if (lane == 0) s_c2[wid] = acc;
    }
    __syncthreads();

    // ---- main: each warp handles 4 rows, 2 at a time ----
    const int row_base = blockIdx.x * ROWS_PER_BLOCK + wid * 4;
    const float4* cbase = reinterpret_cast<const float4*>(s_comp);

    #pragma unroll
    for (int rp = 0; rp < 2; ++rp) {
        const int r0 = row_base + rp * 2;
        const int r1 = r0 + 1;
        if (r0 >= B) break;
        const bool have_r1 = (r1 < B);

        const float4* x0p = reinterpret_cast<const float4*>(x + (size_t)r0 * D_DIM);
        const float4* x1p = reinterpret_cast<const float4*>(x + (size_t)(have_r1 ? r1 : r0) * D_DIM);

        // acc[0..5]  : row0  (xx, dot0..dot4)
        // acc[6..11] : row1
        float acc[12];
        #pragma unroll
        for (int i = 0; i < 12; ++i) acc[i] = 0.f;

        #pragma unroll
        for (int j = 0; j < F4_PER_LANE; ++j) {
            const int idx = lane + 32 * j;
            float4 a = x0p[idx];
            float4 b = x1p[idx];
            acc[0] += a.x * a.x + a.y * a.y + a.z * a.z + a.w * a.w;
            acc[6] += b.x * b.x + b.y * b.y + b.z * b.z + b.w * b.w;
            #pragma unroll
            for (int k = 0; k < K_DIM; ++k) {
                float4 cv = cbase[k * F4_PER_ROW + idx];
                acc[1 + k] += a.x * cv.x + a.y * cv.y + a.z * cv.z + a.w * cv.w;
                acc[7 + k] += b.x * cv.x + b.y * cv.y + b.z * cv.z + b.w * cv.w;
            }
        }

        // warp butterfly reduction of all 12 accumulators
        #pragma unroll
        for (int i = 0; i < 12; ++i) {
            #pragma unroll
            for (int off = 16; off; off >>= 1)
                acc[i] += __shfl_xor_sync(0xffffffffu, acc[i], off);
        }

        if (lane == 0) {
            #pragma unroll
            for (int rr = 0; rr < 2; ++rr) {
                const int r = (rr == 0) ? r0 : r1;
                if (rr == 1 && !have_r1) break;
                const float xx = acc[rr * 6 + 0];
                float num[C_DIM];
                #pragma unroll
                for (int c = 0; c < C_DIM; ++c) num[c] = s_bias[c];
                #pragma unroll
                for (int k = 0; k < K_DIM; ++k) {
                    float d2 = xx + s_c2[k] - 2.f * acc[rr * 6 + 1 + k];
                    d2 = fmaxf(d2, 0.f);
                    float s = __expf(-0.5f * d2);
                    #pragma unroll
                    for (int c = 0; c < C_DIM; ++c) num[c] += s * s_W[c][k];
                }
                #pragma unroll
                for (int c = 0; c < C_DIM; ++c)
                    out[(size_t)r * C_DIM + c] = num[c] * s_rden[c];
            }
        }
    }
}

extern "C" void kernel_launch(void* const* d_in, const int* in_sizes, int n_in,
                              void* d_out, int out_size)
{
    const float* x     = (const float*)d_in[0];
    const float* comps = (const float*)d_in[1];
    const float* reas  = (const float*)d_in[2];
    float* out = (float*)d_out;

    const int B = in_sizes[0] / D_DIM;          // 32768
    const int grid = (B + ROWS_PER_BLOCK - 1) / ROWS_PER_BLOCK;  // 1024
    cbc_kernel<<<grid, THREADS>>>(x, comps, reas, out, B);
}

// round 2
// speedup vs baseline: 1.1573x; 1.1573x over previous
#include <cuda_runtime.h>
#include <cuda_bf16.h>

// CBC_34033320854004  — R2: occupancy fix (128-reg cap, 2 CTA/SM, single pass/warp)
// x           : [B, 1024] f32
// components  : [5, 1024] f32
// reasonings  : [5, 3, 2] f32
// out (probs) : [B, 3]    f32

#define D_DIM 1024
#define K_DIM 5
#define C_DIM 3
#define THREADS 256
#define ROWS_PER_BLOCK 16              // 8 warps * 2 rows, single pass
#define F4_PER_ROW (D_DIM / 4)         // 256 float4 per row
#define F4_PER_LANE (F4_PER_ROW / 32)  // 8 float4 per lane

__global__ __launch_bounds__(THREADS, 2)
void cbc_kernel(const float* __restrict__ x,
                const float* __restrict__ comps,
                const float* __restrict__ reas,
                float* __restrict__ out,
                int B)
{
    __shared__ float s_comp[K_DIM * D_DIM];   // 20 KB
    __shared__ float s_c2[K_DIM];
    __shared__ float s_W[C_DIM][K_DIM];       // pk - nk
    __shared__ float s_bias[C_DIM];           // sum_k nk
    __shared__ float s_rden[C_DIM];           // 1 / sum_k (pk + nk)

    const int tid  = threadIdx.x;
    const int wid  = tid >> 5;
    const int lane = tid & 31;

    // ---- stage components into shared (vectorized) ----
    {
        const float4* src = reinterpret_cast<const float4*>(comps);
        float4* dst = reinterpret_cast<float4*>(s_comp);
        #pragma unroll
        for (int i = tid; i < K_DIM * F4_PER_ROW; i += THREADS)
            dst[i] = src[i];
    }

    // ---- reasonings -> W, bias, rden (tiny; one thread) ----
    if (tid == 0) {
        #pragma unroll
        for (int c = 0; c < C_DIM; ++c) {
            float bias = 0.f, den = 0.f;
            #pragma unroll
            for (int k = 0; k < K_DIM; ++k) {
                float A  = reas[(k * C_DIM + c) * 2 + 0];
                float Bn = reas[(k * C_DIM + c) * 2 + 1];
                A  = fminf(fmaxf(A,  0.f), 1.f);
                Bn = fminf(fmaxf(Bn, 0.f), 1.f);
                float pk = A;
                float nk = (1.f - A) * Bn;
                s_W[c][k] = pk - nk;
                bias += nk;
                den  += pk + nk;
            }
            s_bias[c] = bias;
            s_rden[c] = 1.f / den;
        }
    }
    __syncthreads();

    // ---- c2[k]: one warp per component ----
    if (wid < K_DIM) {
        float acc = 0.f;
        const float4* cp = reinterpret_cast<const float4*>(s_comp + wid * D_DIM);
        #pragma unroll
        for (int j = 0; j < F4_PER_LANE; ++j) {
            float4 v = cp[lane + 32 * j];
            acc += v.x * v.x + v.y * v.y + v.z * v.z + v.w * v.w;
        }
        #pragma unroll
        for (int off = 16; off; off >>= 1)
            acc += __shfl_xor_sync(0xffffffffu, acc, off);
        if (lane == 0) s_c2[wid] = acc;
    }
    __syncthreads();

    // ---- main: each warp reduces 2 rows jointly (amortizes the shared comp loads) ----
    const int r0 = blockIdx.x * ROWS_PER_BLOCK + wid * 2;
    const int r1 = r0 + 1;
    if (r0 >= B) return;
    const bool have_r1 = (r1 < B);

    const float4* x0p = reinterpret_cast<const float4*>(x + (size_t)r0 * D_DIM);
    const float4* x1p = reinterpret_cast<const float4*>(x + (size_t)(have_r1 ? r1 : r0) * D_DIM);
    const float4* cbase = reinterpret_cast<const float4*>(s_comp);

    // acc[0..5]  : row0  (xx, dot0..dot4) ; acc[6..11] : row1
    float acc[12];
    #pragma unroll
    for (int i = 0; i < 12; ++i) acc[i] = 0.f;

    #pragma unroll
    for (int j = 0; j < F4_PER_LANE; ++j) {
        const int idx = lane + 32 * j;
        float4 a = x0p[idx];
        float4 b = x1p[idx];
        acc[0] += a.x * a.x + a.y * a.y + a.z * a.z + a.w * a.w;
        acc[6] += b.x * b.x + b.y * b.y + b.z * b.z + b.w * b.w;
        #pragma unroll
        for (int k = 0; k < K_DIM; ++k) {
            float4 cv = cbase[k * F4_PER_ROW + idx];
            acc[1 + k] += a.x * cv.x + a.y * cv.y + a.z * cv.z + a.w * cv.w;
            acc[7 + k] += b.x * cv.x + b.y * cv.y + b.z * cv.z + b.w * cv.w;
        }
    }

    // warp butterfly reduction of all 12 accumulators
    #pragma unroll
    for (int i = 0; i < 12; ++i) {
        #pragma unroll
        for (int off = 16; off; off >>= 1)
            acc[i] += __shfl_xor_sync(0xffffffffu, acc[i], off);
    }

    if (lane == 0) {
        #pragma unroll
        for (int rr = 0; rr < 2; ++rr) {
            if (rr == 1 && !have_r1) break;
            const int r = r0 + rr;
            const float xx = acc[rr * 6 + 0];
            float num[C_DIM];
            #pragma unroll
            for (int c = 0; c < C_DIM; ++c) num[c] = s_bias[c];
            #pragma unroll
            for (int k = 0; k < K_DIM; ++k) {
                float d2 = xx + s_c2[k] - 2.f * acc[rr * 6 + 1 + k];
                d2 = fmaxf(d2, 0.f);
                float s = __expf(-0.5f * d2);
                #pragma unroll
                for (int c = 0; c < C_DIM; ++c) num[c] += s * s_W[c][k];
            }
            #pragma unroll
            for (int c = 0; c < C_DIM; ++c)
                out[(size_t)r * C_DIM + c] = num[c] * s_rden[c];
        }
    }
}

extern "C" void kernel_launch(void* const* d_in, const int* in_sizes, int n_in,
                              void* d_out, int out_size)
{
    const float* x     = (const float*)d_in[0];
    const float* comps = (const float*)d_in[1];
    const float* reas  = (const float*)d_in[2];
    float* out = (float*)d_out;

    const int B = in_sizes[0] / D_DIM;          // 32768
    const int grid = (B + ROWS_PER_BLOCK - 1) / ROWS_PER_BLOCK;  // 2048
    cbc_kernel<<<grid, THREADS>>>(x, comps, reas, out, B);
}

// round 3
// speedup vs baseline: 1.2328x; 1.0652x over previous
#include <cuda_runtime.h>
#include <cuda_bf16.h>

// CBC_34033320854004 — R3: 4 rows per warp (halve LDS/row, 4x LDG MLP per step)
// x           : [B, 1024] f32
// components  : [5, 1024] f32
// reasonings  : [5, 3, 2] f32
// out (probs) : [B, 3]    f32

#define D_DIM 1024
#define K_DIM 5
#define C_DIM 3
#define THREADS 256
#define ROWS_PER_WARP 4
#define ROWS_PER_BLOCK 32              // 8 warps * 4 rows
#define F4_PER_ROW (D_DIM / 4)         // 256 float4 per row
#define F4_PER_LANE (F4_PER_ROW / 32)  // 8 float4 per lane

__global__ __launch_bounds__(THREADS, 2)
void cbc_kernel(const float* __restrict__ x,
                const float* __restrict__ comps,
                const float* __restrict__ reas,
                float* __restrict__ out,
                int B)
{
    __shared__ float s_comp[K_DIM * D_DIM];   // 20 KB
    __shared__ float s_c2[K_DIM];
    __shared__ float s_W[C_DIM][K_DIM];       // pk - nk
    __shared__ float s_bias[C_DIM];           // sum_k nk
    __shared__ float s_rden[C_DIM];           // 1 / sum_k (pk + nk)

    const int tid  = threadIdx.x;
    const int wid  = tid >> 5;
    const int lane = tid & 31;

    // ---- stage components into shared (vectorized) ----
    {
        const float4* src = reinterpret_cast<const float4*>(comps);
        float4* dst = reinterpret_cast<float4*>(s_comp);
        #pragma unroll
        for (int i = tid; i < K_DIM * F4_PER_ROW; i += THREADS)
            dst[i] = src[i];
    }

    // ---- reasonings -> W, bias, rden (tiny; one thread) ----
    if (tid == 0) {
        #pragma unroll
        for (int c = 0; c < C_DIM; ++c) {
            float bias = 0.f, den = 0.f;
            #pragma unroll
            for (int k = 0; k < K_DIM; ++k) {
                float A  = reas[(k * C_DIM + c) * 2 + 0];
                float Bn = reas[(k * C_DIM + c) * 2 + 1];
                A  = fminf(fmaxf(A,  0.f), 1.f);
                Bn = fminf(fmaxf(Bn, 0.f), 1.f);
                float pk = A;
                float nk = (1.f - A) * Bn;
                s_W[c][k] = pk - nk;
                bias += nk;
                den  += pk + nk;
            }
            s_bias[c] = bias;
            s_rden[c] = 1.f / den;
        }
    }
    __syncthreads();

    // ---- c2[k]: one warp per component ----
    if (wid < K_DIM) {
        float acc = 0.f;
        const float4* cp = reinterpret_cast<const float4*>(s_comp + wid * D_DIM);
        #pragma unroll
        for (int j = 0; j < F4_PER_LANE; ++j) {
            float4 v = cp[lane + 32 * j];
            acc += v.x * v.x + v.y * v.y + v.z * v.z + v.w * v.w;
        }
        #pragma unroll
        for (int off = 16; off; off >>= 1)
            acc += __shfl_xor_sync(0xffffffffu, acc, off);
        if (lane == 0) s_c2[wid] = acc;
    }
    __syncthreads();

    // ---- main: each warp reduces 4 rows jointly (amortizes component LDS) ----
    const int r0 = blockIdx.x * ROWS_PER_BLOCK + wid * ROWS_PER_WARP;
    if (r0 >= B) return;
    // B = 32768 is a multiple of 32, so the whole 4-row group is in range when r0 < B.

    const float4* xp[ROWS_PER_WARP];
    #pragma unroll
    for (int rr = 0; rr < ROWS_PER_WARP; ++rr)
        xp[rr] = reinterpret_cast<const float4*>(x + (size_t)(r0 + rr) * D_DIM);
    const float4* cbase = reinterpret_cast<const float4*>(s_comp);

    // acc layout: [row][0] = xx, [row][1+k] = dot_k
    float acc[ROWS_PER_WARP][K_DIM + 1];
    #pragma unroll
    for (int rr = 0; rr < ROWS_PER_WARP; ++rr)
        #pragma unroll
        for (int i = 0; i <= K_DIM; ++i) acc[rr][i] = 0.f;

    #pragma unroll
    for (int j = 0; j < F4_PER_LANE; ++j) {
        const int idx = lane + 32 * j;
        float4 v[ROWS_PER_WARP];
        #pragma unroll
        for (int rr = 0; rr < ROWS_PER_WARP; ++rr)
            v[rr] = xp[rr][idx];
        #pragma unroll
        for (int rr = 0; rr < ROWS_PER_WARP; ++rr)
            acc[rr][0] += v[rr].x * v[rr].x + v[rr].y * v[rr].y
                        + v[rr].z * v[rr].z + v[rr].w * v[rr].w;
        #pragma unroll
        for (int k = 0; k < K_DIM; ++k) {
            float4 cv = cbase[k * F4_PER_ROW + idx];
            #pragma unroll
            for (int rr = 0; rr < ROWS_PER_WARP; ++rr)
                acc[rr][1 + k] += v[rr].x * cv.x + v[rr].y * cv.y
                                + v[rr].z * cv.z + v[rr].w * cv.w;
        }
    }

    // warp butterfly reduction of all 24 accumulators
    #pragma unroll
    for (int rr = 0; rr < ROWS_PER_WARP; ++rr)
        #pragma unroll
        for (int i = 0; i <= K_DIM; ++i)
            #pragma unroll
            for (int off = 16; off; off >>= 1)
                acc[rr][i] += __shfl_xor_sync(0xffffffffu, acc[rr][i], off);

    if (lane == 0) {
        #pragma unroll
        for (int rr = 0; rr < ROWS_PER_WARP; ++rr) {
            const int r = r0 + rr;
            const float xx = acc[rr][0];
            float num[C_DIM];
            #pragma unroll
            for (int c = 0; c < C_DIM; ++c) num[c] = s_bias[c];
            #pragma unroll
            for (int k = 0; k < K_DIM; ++k) {
                float d2 = xx + s_c2[k] - 2.f * acc[rr][1 + k];
                d2 = fmaxf(d2, 0.f);
                float s = __expf(-0.5f * d2);
                #pragma unroll
                for (int c = 0; c < C_DIM; ++c) num[c] += s * s_W[c][k];
            }
            #pragma unroll
            for (int c = 0; c < C_DIM; ++c)
                out[(size_t)r * C_DIM + c] = num[c] * s_rden[c];
        }
    }
}

extern "C" void kernel_launch(void* const* d_in, const int* in_sizes, int n_in,
                              void* d_out, int out_size)
{
    const float* x     = (const float*)d_in[0];
    const float* comps = (const float*)d_in[1];
    const float* reas  = (const float*)d_in[2];
    float* out = (float*)d_out;

    const int B = in_sizes[0] / D_DIM;          // 32768
    const int grid = (B + ROWS_PER_BLOCK - 1) / ROWS_PER_BLOCK;  // 1024
    cbc_kernel<<<grid, THREADS>>>(x, comps, reas, out, B);
}

// round 4
// speedup vs baseline: 1.2463x; 1.0110x over previous
#include <cuda_runtime.h>
#include <cuda_bf16.h>

// CBC_34033320854004 — R4: 3 CTAs/SM (84-reg cap) + single-base immediate-offset loads
// x           : [B, 1024] f32
// components  : [5, 1024] f32
// reasonings  : [5, 3, 2] f32
// out (probs) : [B, 3]    f32

#define D_DIM 1024
#define K_DIM 5
#define C_DIM 3
#define THREADS 256
#define ROWS_PER_WARP 4
#define ROWS_PER_BLOCK 32              // 8 warps * 4 rows
#define F4_PER_ROW (D_DIM / 4)         // 256 float4 per row
#define F4_PER_LANE (F4_PER_ROW / 32)  // 8 float4 per lane

__global__ __launch_bounds__(THREADS, 3)
void cbc_kernel(const float* __restrict__ x,
                const float* __restrict__ comps,
                const float* __restrict__ reas,
                float* __restrict__ out,
                int B)
{
    __shared__ float s_comp[K_DIM * D_DIM];   // 20 KB
    __shared__ float s_c2[K_DIM];
    __shared__ float s_W[C_DIM][K_DIM];       // pk - nk
    __shared__ float s_bias[C_DIM];           // sum_k nk
    __shared__ float s_rden[C_DIM];           // 1 / sum_k (pk + nk)

    const int tid  = threadIdx.x;
    const int wid  = tid >> 5;
    const int lane = tid & 31;

    // ---- stage components into shared (vectorized) ----
    {
        const float4* src = reinterpret_cast<const float4*>(comps);
        float4* dst = reinterpret_cast<float4*>(s_comp);
        #pragma unroll
        for (int i = tid; i < K_DIM * F4_PER_ROW; i += THREADS)
            dst[i] = src[i];
    }

    // ---- reasonings -> W, bias, rden (tiny; one thread) ----
    if (tid == 0) {
        #pragma unroll
        for (int c = 0; c < C_DIM; ++c) {
            float bias = 0.f, den = 0.f;
            #pragma unroll
            for (int k = 0; k < K_DIM; ++k) {
                float A  = reas[(k * C_DIM + c) * 2 + 0];
                float Bn = reas[(k * C_DIM + c) * 2 + 1];
                A  = fminf(fmaxf(A,  0.f), 1.f);
                Bn = fminf(fmaxf(Bn, 0.f), 1.f);
                float pk = A;
                float nk = (1.f - A) * Bn;
                s_W[c][k] = pk - nk;
                bias += nk;
                den  += pk + nk;
            }
            s_bias[c] = bias;
            s_rden[c] = 1.f / den;
        }
    }
    __syncthreads();

    // ---- c2[k]: one warp per component ----
    if (wid < K_DIM) {
        float acc = 0.f;
        const float4* cp = reinterpret_cast<const float4*>(s_comp + wid * D_DIM);
        #pragma unroll
        for (int j = 0; j < F4_PER_LANE; ++j) {
            float4 v = cp[lane + 32 * j];
            acc += v.x * v.x + v.y * v.y + v.z * v.z + v.w * v.w;
        }
        #pragma unroll
        for (int off = 16; off; off >>= 1)
            acc += __shfl_xor_sync(0xffffffffu, acc, off);
        if (lane == 0) s_c2[wid] = acc;
    }
    __syncthreads();

    // ---- main: each warp reduces 4 consecutive rows jointly ----
    const int r0 = blockIdx.x * ROWS_PER_BLOCK + wid * ROWS_PER_WARP;
    if (r0 >= B) return;
    // B is a multiple of 32, so the whole 4-row group is in range when r0 < B.

    // Single base pointer: all global loads are [base + compile-time-imm].
    const float4* __restrict__ xbase =
        reinterpret_cast<const float4*>(x + (size_t)r0 * D_DIM) + lane;
    // Single shared base: all LDS are [sbase + compile-time-imm].
    const float4* __restrict__ sbase =
        reinterpret_cast<const float4*>(s_comp) + lane;

    // acc layout: [row][0] = xx, [row][1+k] = dot_k
    float acc[ROWS_PER_WARP][K_DIM + 1];
    #pragma unroll
    for (int rr = 0; rr < ROWS_PER_WARP; ++rr)
        #pragma unroll
        for (int i = 0; i <= K_DIM; ++i) acc[rr][i] = 0.f;

    #pragma unroll
    for (int j = 0; j < F4_PER_LANE; ++j) {
        float4 v[ROWS_PER_WARP];
        #pragma unroll
        for (int rr = 0; rr < ROWS_PER_WARP; ++rr)
            v[rr] = xbase[rr * F4_PER_ROW + 32 * j];   // imm offsets: rr*4KB + j*512B
        #pragma unroll
        for (int rr = 0; rr < ROWS_PER_WARP; ++rr)
            acc[rr][0] += v[rr].x * v[rr].x + v[rr].y * v[rr].y
                        + v[rr].z * v[rr].z + v[rr].w * v[rr].w;
        #pragma unroll
        for (int k = 0; k < K_DIM; ++k) {
            float4 cv = sbase[k * F4_PER_ROW + 32 * j]; // imm offsets
            #pragma unroll
            for (int rr = 0; rr < ROWS_PER_WARP; ++rr)
                acc[rr][1 + k] += v[rr].x * cv.x + v[rr].y * cv.y
                                + v[rr].z * cv.z + v[rr].w * cv.w;
        }
    }

    // warp butterfly reduction of all 24 accumulators
    #pragma unroll
    for (int rr = 0; rr < ROWS_PER_WARP; ++rr)
        #pragma unroll
        for (int i = 0; i <= K_DIM; ++i)
            #pragma unroll
            for (int off = 16; off; off >>= 1)
                acc[rr][i] += __shfl_xor_sync(0xffffffffu, acc[rr][i], off);

    if (lane == 0) {
        #pragma unroll
        for (int rr = 0; rr < ROWS_PER_WARP; ++rr) {
            const int r = r0 + rr;
            const float xx = acc[rr][0];
            float num[C_DIM];
            #pragma unroll
            for (int c = 0; c < C_DIM; ++c) num[c] = s_bias[c];
            #pragma unroll
            for (int k = 0; k < K_DIM; ++k) {
                float d2 = xx + s_c2[k] - 2.f * acc[rr][1 + k];
                d2 = fmaxf(d2, 0.f);
                float s = __expf(-0.5f * d2);
                #pragma unroll
                for (int c = 0; c < C_DIM; ++c) num[c] += s * s_W[c][k];
            }
            #pragma unroll
            for (int c = 0; c < C_DIM; ++c)
                out[(size_t)r * C_DIM + c] = num[c] * s_rden[c];
        }
    }
}

extern "C" void kernel_launch(void* const* d_in, const int* in_sizes, int n_in,
                              void* d_out, int out_size)
{
    const float* x     = (const float*)d_in[0];
    const float* comps = (const float*)d_in[1];
    const float* reas  = (const float*)d_in[2];
    float* out = (float*)d_out;

    const int B = in_sizes[0] / D_DIM;          // 32768
    const int grid = (B + ROWS_PER_BLOCK - 1) / ROWS_PER_BLOCK;  // 1024
    cbc_kernel<<<grid, THREADS>>>(x, comps, reas, out, B);
}

// round 5
// speedup vs baseline: 1.3087x; 1.0500x over previous
#include <cuda_runtime.h>
#include <cuda_bf16.h>

// CBC_34033320854004 — R5: persistent CTAs + atomic 4-row work queue (kill wave tail)
// x           : [B, 1024] f32
// components  : [5, 1024] f32
// reasonings  : [5, 3, 2] f32
// out (probs) : [B, 3]    f32

#define D_DIM 1024
#define K_DIM 5
#define C_DIM 3
#define THREADS 256
#define ROWS_PER_TASK 4
#define F4_PER_ROW (D_DIM / 4)         // 256 float4 per row
#define F4_PER_LANE (F4_PER_ROW / 32)  // 8 float4 per lane
#define NUM_SMS 148
#define CTAS_PER_SM 3
#define GRID_PERSIST (NUM_SMS * CTAS_PER_SM)   // 444

__device__ unsigned int g_ticket;

__global__ void reset_ticket_kernel() { g_ticket = 0u; }

__global__ __launch_bounds__(THREADS, CTAS_PER_SM)
void cbc_kernel(const float* __restrict__ x,
                const float* __restrict__ comps,
                const float* __restrict__ reas,
                float* __restrict__ out,
                int B)
{
    __shared__ float s_comp[K_DIM * D_DIM];   // 20 KB
    __shared__ float s_c2[K_DIM];
    __shared__ float s_W[C_DIM][K_DIM];       // pk - nk
    __shared__ float s_bias[C_DIM];           // sum_k nk
    __shared__ float s_rden[C_DIM];           // 1 / sum_k (pk + nk)

    const int tid  = threadIdx.x;
    const int wid  = tid >> 5;
    const int lane = tid & 31;

    // ---- stage components into shared (vectorized; once per persistent CTA) ----
    {
        const float4* src = reinterpret_cast<const float4*>(comps);
        float4* dst = reinterpret_cast<float4*>(s_comp);
        #pragma unroll
        for (int i = tid; i < K_DIM * F4_PER_ROW; i += THREADS)
            dst[i] = src[i];
    }

    // ---- reasonings -> W, bias, rden (tiny; one thread) ----
    if (tid == 0) {
        #pragma unroll
        for (int c = 0; c < C_DIM; ++c) {
            float bias = 0.f, den = 0.f;
            #pragma unroll
            for (int k = 0; k < K_DIM; ++k) {
                float A  = reas[(k * C_DIM + c) * 2 + 0];
                float Bn = reas[(k * C_DIM + c) * 2 + 1];
                A  = fminf(fmaxf(A,  0.f), 1.f);
                Bn = fminf(fmaxf(Bn, 0.f), 1.f);
                float pk = A;
                float nk = (1.f - A) * Bn;
                s_W[c][k] = pk - nk;
                bias += nk;
                den  += pk + nk;
            }
            s_bias[c] = bias;
            s_rden[c] = 1.f / den;
        }
    }
    __syncthreads();

    // ---- c2[k]: one warp per component ----
    if (wid < K_DIM) {
        float acc = 0.f;
        const float4* cp = reinterpret_cast<const float4*>(s_comp + wid * D_DIM);
        #pragma unroll
        for (int j = 0; j < F4_PER_LANE; ++j) {
            float4 v = cp[lane + 32 * j];
            acc += v.x * v.x + v.y * v.y + v.z * v.z + v.w * v.w;
        }
        #pragma unroll
        for (int off = 16; off; off >>= 1)
            acc += __shfl_xor_sync(0xffffffffu, acc, off);
        if (lane == 0) s_c2[wid] = acc;
    }
    __syncthreads();

    const float4* __restrict__ sbase =
        reinterpret_cast<const float4*>(s_comp) + lane;
    const int n_tasks = (B + ROWS_PER_TASK - 1) / ROWS_PER_TASK;

    // ---- persistent per-warp work loop over 4-row tasks ----
    for (;;) {
        unsigned int t;
        if (lane == 0) t = atomicAdd(&g_ticket, 1u);
        t = __shfl_sync(0xffffffffu, t, 0);
        if (t >= (unsigned int)n_tasks) break;
        const int r0 = (int)t * ROWS_PER_TASK;
        // B = 32768 is a multiple of ROWS_PER_TASK, so the whole group is valid.

        // Single base pointer: all global loads are [base + compile-time-imm].
        const float4* __restrict__ xbase =
            reinterpret_cast<const float4*>(x + (size_t)r0 * D_DIM) + lane;

        // acc layout: [row][0] = xx, [row][1+k] = dot_k
        float acc[ROWS_PER_TASK][K_DIM + 1];
        #pragma unroll
        for (int rr = 0; rr < ROWS_PER_TASK; ++rr)
            #pragma unroll
            for (int i = 0; i <= K_DIM; ++i) acc[rr][i] = 0.f;

        #pragma unroll
        for (int j = 0; j < F4_PER_LANE; ++j) {
            float4 v[ROWS_PER_TASK];
            #pragma unroll
            for (int rr = 0; rr < ROWS_PER_TASK; ++rr)
                v[rr] = xbase[rr * F4_PER_ROW + 32 * j];  // imm offsets
            #pragma unroll
            for (int rr = 0; rr < ROWS_PER_TASK; ++rr)
                acc[rr][0] += v[rr].x * v[rr].x + v[rr].y * v[rr].y
                            + v[rr].z * v[rr].z + v[rr].w * v[rr].w;
            #pragma unroll
            for (int k = 0; k < K_DIM; ++k) {
                float4 cv = sbase[k * F4_PER_ROW + 32 * j];  // imm offsets
                #pragma unroll
                for (int rr = 0; rr < ROWS_PER_TASK; ++rr)
                    acc[rr][1 + k] += v[rr].x * cv.x + v[rr].y * cv.y
                                    + v[rr].z * cv.z + v[rr].w * cv.w;
            }
        }

        // warp butterfly reduction of all 24 accumulators
        #pragma unroll
        for (int rr = 0; rr < ROWS_PER_TASK; ++rr)
            #pragma unroll
            for (int i = 0; i <= K_DIM; ++i)
                #pragma unroll
                for (int off = 16; off; off >>= 1)
                    acc[rr][i] += __shfl_xor_sync(0xffffffffu, acc[rr][i], off);

        if (lane == 0) {
            #pragma unroll
            for (int rr = 0; rr < ROWS_PER_TASK; ++rr) {
                const int r = r0 + rr;
                const float xx = acc[rr][0];
                float num[C_DIM];
                #pragma unroll
                for (int c = 0; c < C_DIM; ++c) num[c] = s_bias[c];
                #pragma unroll
                for (int k = 0; k < K_DIM; ++k) {
                    float d2 = xx + s_c2[k] - 2.f * acc[rr][1 + k];
                    d2 = fmaxf(d2, 0.f);
                    float s = __expf(-0.5f * d2);
                    #pragma unroll
                    for (int c = 0; c < C_DIM; ++c) num[c] += s * s_W[c][k];
                }
                #pragma unroll
                for (int c = 0; c < C_DIM; ++c)
                    out[(size_t)r * C_DIM + c] = num[c] * s_rden[c];
            }
        }
    }
}

extern "C" void kernel_launch(void* const* d_in, const int* in_sizes, int n_in,
                              void* d_out, int out_size)
{
    const float* x     = (const float*)d_in[0];
    const float* comps = (const float*)d_in[1];
    const float* reas  = (const float*)d_in[2];
    float* out = (float*)d_out;

    const int B = in_sizes[0] / D_DIM;          // 32768

    reset_ticket_kernel<<<1, 1>>>();
    cbc_kernel<<<GRID_PERSIST, THREADS>>>(x, comps, reas, out, B);
}